// round 1
// baseline (speedup 1.0000x reference)
#include <cuda_runtime.h>
#include <math.h>

#define ALPHA 10.0f
#define NPTS 4096
#define NB 4
#define BLOCK 256

// Scratch (no device mallocs allowed): row-mins for both directions, and
// per-(dir,batch) logsumexp results.
__device__ float g_min[2 * NB * NPTS];
__device__ float g_lse[2 * NB];

// ---------------------------------------------------------------------------
// Kernel 1: for each (dir, batch, row i) compute min_j ||a_i - b_j||^2.
// dir=0: rows from p1, candidates from p2. dir=1: swapped.
// Candidates cached in smem as float4{x, y, z, 0.5*||b||^2} so the inner loop
// is 1 LDS.128 + 3 FFMA + 1 FMNMX per pair:
//   min_j dist = sq1_i - 2 * max_j( a.x*b.x + a.y*b.y + a.z*b.z - 0.5*sq2_j )
// ---------------------------------------------------------------------------
__global__ void hausdorff_min_kernel(const float* __restrict__ p1,
                                     const float* __restrict__ p2)
{
    extern __shared__ float4 sB[];   // NPTS * 16B = 64 KB

    const int b   = blockIdx.y;
    const int dir = blockIdx.z;
    const float* __restrict__ A  = dir ? p2 : p1;
    const float* __restrict__ Bv = dir ? p1 : p2;
    const float* __restrict__ Bb = Bv + (size_t)b * NPTS * 3;

    const int tid = threadIdx.x;

    // Cooperative load + transform of the candidate set into smem.
    for (int j = tid; j < NPTS; j += BLOCK) {
        float x = Bb[3 * j + 0];
        float y = Bb[3 * j + 1];
        float z = Bb[3 * j + 2];
        sB[j] = make_float4(x, y, z, 0.5f * (x * x + y * y + z * z));
    }
    __syncthreads();

    const int i = blockIdx.x * BLOCK + tid;
    const float* __restrict__ Ai = A + ((size_t)b * NPTS + i) * 3;
    const float ax = Ai[0];
    const float ay = Ai[1];
    const float az = Ai[2];

    float best = -3.402823466e38f;
#pragma unroll 8
    for (int j = 0; j < NPTS; ++j) {
        float4 p = sB[j];
        float s = fmaf(ax, p.x, -p.w);
        s = fmaf(ay, p.y, s);
        s = fmaf(az, p.z, s);
        best = fmaxf(best, s);
    }

    const float sq1 = ax * ax + ay * ay + az * az;
    g_min[((size_t)dir * NB + b) * NPTS + i] = sq1 - 2.0f * best;
}

// ---------------------------------------------------------------------------
// Kernel 2: per-(dir,batch) logsumexp(ALPHA * min) / ALPHA over NPTS values.
// One block per group (8 groups total).
// ---------------------------------------------------------------------------
__global__ void hausdorff_lse_kernel()
{
    __shared__ float red[BLOCK];

    const int g = blockIdx.x;              // 0..7 = dir*NB + b
    const float* __restrict__ v = g_min + (size_t)g * NPTS;
    const int tid = threadIdx.x;

    // Pass 1: max of ALPHA * v
    float m = -3.402823466e38f;
    for (int j = tid; j < NPTS; j += BLOCK)
        m = fmaxf(m, ALPHA * v[j]);
    red[tid] = m;
    __syncthreads();
    for (int s = BLOCK / 2; s > 0; s >>= 1) {
        if (tid < s) red[tid] = fmaxf(red[tid], red[tid + s]);
        __syncthreads();
    }
    const float M = red[0];
    __syncthreads();

    // Pass 2: sum of exp(ALPHA*v - M)
    float acc = 0.0f;
    for (int j = tid; j < NPTS; j += BLOCK)
        acc += expf(ALPHA * v[j] - M);
    red[tid] = acc;
    __syncthreads();
    for (int s = BLOCK / 2; s > 0; s >>= 1) {
        if (tid < s) red[tid] += red[tid + s];
        __syncthreads();
    }

    if (tid == 0)
        g_lse[g] = (M + logf(red[0])) / ALPHA;
}

// ---------------------------------------------------------------------------
// Kernel 3: final scalar = (mean_b lse[0][b] + mean_b lse[1][b]) / 2
// ---------------------------------------------------------------------------
__global__ void hausdorff_final_kernel(float* __restrict__ out)
{
    if (threadIdx.x == 0) {
        float a = 0.0f, c = 0.0f;
        for (int i = 0; i < NB; ++i) {
            a += g_lse[i];
            c += g_lse[NB + i];
        }
        out[0] = 0.5f * (a / NB + c / NB);
    }
}

// ---------------------------------------------------------------------------
extern "C" void kernel_launch(void* const* d_in, const int* in_sizes, int n_in,
                              void* d_out, int out_size)
{
    const float* p1 = (const float*)d_in[0];
    const float* p2 = (const float*)d_in[1];
    float* out = (float*)d_out;

    const int smem = NPTS * (int)sizeof(float4);  // 64 KB, needs opt-in
    cudaFuncSetAttribute(hausdorff_min_kernel,
                         cudaFuncAttributeMaxDynamicSharedMemorySize, smem);

    dim3 grid(NPTS / BLOCK, NB, 2);   // 16 x 4 x 2 = 128 blocks
    hausdorff_min_kernel<<<grid, BLOCK, smem>>>(p1, p2);
    hausdorff_lse_kernel<<<2 * NB, BLOCK>>>();
    hausdorff_final_kernel<<<1, 32>>>(out);
}

// round 3
// speedup vs baseline: 1.2225x; 1.2225x over previous
#include <cuda_runtime.h>
#include <math.h>

#define ALPHA 10.0f
#define NPTS  4096
#define NB    4
#define NG    (2 * NB)            // dir * batch groups = 8

#define BLOCK 128                 // threads per block (kernel 1)
#define RPT   8                   // rows per thread
#define JC    16                  // candidate chunks
#define CHUNK (NPTS / JC)         // 256 candidates per chunk
#define ROWTILES (NPTS / (BLOCK * RPT))  // 4

#define LSE_BLOCK 256
#define LSE_RPT   (NPTS / LSE_BLOCK)     // 16

// Scratch: partial row maxima of (a.b - 0.5||b||^2) per (group, chunk, row).
__device__ float g_part[NG * JC * NPTS];   // 2 MB
__device__ float g_lse[NG];

// ---------------------------------------------------------------------------
// Packed fp32x2 helpers (sm_100a native)
// ---------------------------------------------------------------------------
__device__ __forceinline__ unsigned long long ffma2(unsigned long long a,
                                                    unsigned long long b,
                                                    unsigned long long c)
{
    unsigned long long d;
    asm("fma.rn.f32x2 %0, %1, %2, %3;" : "=l"(d) : "l"(a), "l"(b), "l"(c));
    return d;
}

__device__ __forceinline__ unsigned long long pack2(float lo, float hi)
{
    unsigned long long r;
    asm("mov.b64 %0, {%1, %2};" : "=l"(r) : "f"(lo), "f"(hi));
    return r;
}

__device__ __forceinline__ void unpack2(unsigned long long v, float& lo, float& hi)
{
    asm("mov.b64 {%0, %1}, %2;" : "=f"(lo), "=f"(hi) : "l"(v));
}

// ---------------------------------------------------------------------------
// Kernel 1: partial maxima.
// For group g = dir*NB + b, chunk jc, each thread owns 8 rows of A and scans
// CHUNK candidates of B held in smem pre-duplicated for f32x2:
//   per candidate j (per thread): 2 x LDS.128, 12 x FFMA2, 8 x FMNMX
//   => 8 row-candidate pairs in 22 warp instructions.
// ---------------------------------------------------------------------------
__global__ void __launch_bounds__(BLOCK)
hausdorff_part_kernel(const float* __restrict__ p1,
                      const float* __restrict__ p2)
{
    // Each candidate: {bx,bx} {by,by} {bz,bz} {-w,-w}  (w = 0.5*||b||^2)
    __shared__ ulonglong2 sB[CHUNK * 2];   // 8 KB

    const int g   = blockIdx.z;            // 0..7
    const int dir = g >> 2;
    const int b   = g & 3;
    const int jc  = blockIdx.y;
    const int tid = threadIdx.x;

    const float* __restrict__ A  = dir ? p2 : p1;
    const float* __restrict__ Bv = dir ? p1 : p2;
    const float* __restrict__ Bb = Bv + ((size_t)b * NPTS + jc * CHUNK) * 3;

    // Fill smem: 2 candidates per thread.
    for (int j = tid; j < CHUNK; j += BLOCK) {
        float x = Bb[3 * j + 0];
        float y = Bb[3 * j + 1];
        float z = Bb[3 * j + 2];
        float w = -0.5f * (x * x + y * y + z * z);
        sB[2 * j + 0] = make_ulonglong2(pack2(x, x), pack2(y, y));
        sB[2 * j + 1] = make_ulonglong2(pack2(z, z), pack2(w, w));
    }
    __syncthreads();

    // Load 8 rows (strided by BLOCK for coalescing) and pack pairs.
    const int rowbase = blockIdx.x * (BLOCK * RPT);
    float ax[RPT], ay[RPT], az[RPT];
#pragma unroll
    for (int k = 0; k < RPT; ++k) {
        const int i = rowbase + tid + k * BLOCK;
        const float* __restrict__ Ai = A + ((size_t)b * NPTS + i) * 3;
        ax[k] = Ai[0];
        ay[k] = Ai[1];
        az[k] = Ai[2];
    }
    unsigned long long pax[RPT / 2], pay[RPT / 2], paz[RPT / 2];
#pragma unroll
    for (int p = 0; p < RPT / 2; ++p) {
        pax[p] = pack2(ax[2 * p], ax[2 * p + 1]);
        pay[p] = pack2(ay[2 * p], ay[2 * p + 1]);
        paz[p] = pack2(az[2 * p], az[2 * p + 1]);
    }

    float m[RPT];
#pragma unroll
    for (int k = 0; k < RPT; ++k) m[k] = -3.402823466e38f;

#pragma unroll 4
    for (int j = 0; j < CHUNK; ++j) {
        const ulonglong2 q0 = sB[2 * j + 0];   // {bx,bx} {by,by}
        const ulonglong2 q1 = sB[2 * j + 1];   // {bz,bz} {-w,-w}
#pragma unroll
        for (int p = 0; p < RPT / 2; ++p) {
            unsigned long long s = ffma2(pax[p], q0.x, q1.y);
            s = ffma2(pay[p], q0.y, s);
            s = ffma2(paz[p], q1.x, s);
            float s0, s1;
            unpack2(s, s0, s1);
            m[2 * p + 0] = fmaxf(m[2 * p + 0], s0);
            m[2 * p + 1] = fmaxf(m[2 * p + 1], s1);
        }
    }

    float* __restrict__ out = g_part + ((size_t)g * JC + jc) * NPTS;
#pragma unroll
    for (int k = 0; k < RPT; ++k)
        out[rowbase + tid + k * BLOCK] = m[k];
}

// ---------------------------------------------------------------------------
// Kernel 2: per-group reduce chunks -> row min dist -> logsumexp.
// ---------------------------------------------------------------------------
__global__ void __launch_bounds__(LSE_BLOCK)
hausdorff_lse_kernel(const float* __restrict__ p1,
                     const float* __restrict__ p2)
{
    __shared__ float red[LSE_BLOCK];

    const int g   = blockIdx.x;
    const int dir = g >> 2;
    const int b   = g & 3;
    const int tid = threadIdx.x;
    const float* __restrict__ A = dir ? p2 : p1;

    float v[LSE_RPT];
#pragma unroll
    for (int r = 0; r < LSE_RPT; ++r) {
        const int i = tid + r * LSE_BLOCK;
        float mx = -3.402823466e38f;
#pragma unroll
        for (int c = 0; c < JC; ++c)
            mx = fmaxf(mx, g_part[((size_t)g * JC + c) * NPTS + i]);
        const float* __restrict__ Ai = A + ((size_t)b * NPTS + i) * 3;
        const float x = Ai[0], y = Ai[1], z = Ai[2];
        const float sq = x * x + y * y + z * z;
        v[r] = ALPHA * (sq - 2.0f * mx);       // ALPHA * min dist
    }

    // max
    float M = v[0];
#pragma unroll
    for (int r = 1; r < LSE_RPT; ++r) M = fmaxf(M, v[r]);
    red[tid] = M;
    __syncthreads();
    for (int s = LSE_BLOCK / 2; s > 0; s >>= 1) {
        if (tid < s) red[tid] = fmaxf(red[tid], red[tid + s]);
        __syncthreads();
    }
    M = red[0];
    __syncthreads();

    // sum exp
    float acc = 0.0f;
#pragma unroll
    for (int r = 0; r < LSE_RPT; ++r) acc += expf(v[r] - M);
    red[tid] = acc;
    __syncthreads();
    for (int s = LSE_BLOCK / 2; s > 0; s >>= 1) {
        if (tid < s) red[tid] += red[tid + s];
        __syncthreads();
    }

    if (tid == 0)
        g_lse[g] = (M + logf(red[0])) / ALPHA;
}

// ---------------------------------------------------------------------------
// Kernel 3: final scalar.
// ---------------------------------------------------------------------------
__global__ void hausdorff_final_kernel(float* __restrict__ out)
{
    if (threadIdx.x == 0) {
        float a = 0.0f, c = 0.0f;
        for (int i = 0; i < NB; ++i) {
            a += g_lse[i];
            c += g_lse[NB + i];
        }
        out[0] = 0.5f * (a / NB + c / NB);
    }
}

// ---------------------------------------------------------------------------
extern "C" void kernel_launch(void* const* d_in, const int* in_sizes, int n_in,
                              void* d_out, int out_size)
{
    const float* p1 = (const float*)d_in[0];
    const float* p2 = (const float*)d_in[1];
    float* out = (float*)d_out;

    dim3 grid(ROWTILES, JC, NG);   // 4 x 16 x 8 = 512 blocks
    hausdorff_part_kernel<<<grid, BLOCK>>>(p1, p2);
    hausdorff_lse_kernel<<<NG, LSE_BLOCK>>>(p1, p2);
    hausdorff_final_kernel<<<1, 32>>>(out);
}